// round 13
// baseline (speedup 1.0000x reference)
#include <cuda_runtime.h>
#include <math.h>
#include <stdint.h>

#define NVERT 2562
#define DEPTH 8
#define CDIM  512
#define NHEAD 8
#define HD    64
#define KNB   8
#define HIDD  2048
#define MTOK  (NVERT*DEPTH)   /* 20496 */
#define MPAD  20608           /* 161*128 */
#define MT    161

// fp32 scratch
__device__ float g_q  [(size_t)MPAD*CDIM];   // q (scaled by 8)
__device__ float g_x2 [(size_t)MPAD*CDIM];
// int8 activation planes (hi, lo)
__device__ int8_t g_xn_h[(size_t)MPAD*CDIM];
__device__ int8_t g_xn_l[(size_t)MPAD*CDIM];
__device__ int8_t g_k_h [(size_t)MPAD*CDIM];
__device__ int8_t g_k_l [(size_t)MPAD*CDIM];
__device__ int8_t g_v_h [(size_t)MPAD*CDIM];
__device__ int8_t g_v_l [(size_t)MPAD*CDIM];
__device__ int8_t g_y_h [(size_t)MPAD*CDIM];
__device__ int8_t g_y_l [(size_t)MPAD*CDIM];
__device__ int8_t g_h_h [(size_t)MPAD*HIDD];
__device__ int8_t g_h_l [(size_t)MPAD*HIDD];
// per-row activation scales (zero-init -> padded rows contribute 0)
__device__ float g_sa1[MPAD];
__device__ float g_sa2[MPAD];
// int8 weight planes + per-row scales
__device__ int8_t g_wqkv_h[(size_t)3*CDIM*CDIM];
__device__ int8_t g_wqkv_l[(size_t)3*CDIM*CDIM];
__device__ int8_t g_wproj_h[(size_t)CDIM*CDIM];
__device__ int8_t g_wproj_l[(size_t)CDIM*CDIM];
__device__ int8_t g_wfc1_h[(size_t)HIDD*CDIM];
__device__ int8_t g_wfc1_l[(size_t)HIDD*CDIM];
__device__ int8_t g_wfc2_h[(size_t)CDIM*HIDD];
__device__ int8_t g_wfc2_l[(size_t)CDIM*HIDD];
__device__ float g_swqkv[3*CDIM];
__device__ float g_swproj[CDIM];
__device__ float g_swfc1[HIDD];
__device__ float g_swfc2[CDIM];

#define S_H  6.0f   /* fixed scale for GELU outputs */
#define S_KV 8.0f   /* fixed scale for K/V planes (values ~N(0,1); 8 = 8 sigma) */

// x ~= s/127 * (h + l/254)
__device__ __forceinline__ void isplit(float x, float inv /* =127/s */,
                                       int8_t& h, int8_t& l) {
    float q = fminf(fmaxf(x * inv, -127.0f), 127.0f);
    int hi = __float2int_rn(q);
    int lo = __float2int_rn((q - (float)hi) * 254.0f);
    h = (int8_t)hi; l = (int8_t)lo;
}

// ---------------------------------------------------------------------------
// Weight quantization: one block (128 thr) per output row; per-row scale.
// ---------------------------------------------------------------------------
__global__ void wq_kernel(const float* __restrict__ w, int8_t* __restrict__ h,
                          int8_t* __restrict__ l, float* __restrict__ sw, int K) {
    int row = blockIdx.x, tid = threadIdx.x;
    const float* wr = w + (size_t)row * K;
    float m = 0.0f;
    for (int j = tid; j < K; j += 128) m = fmaxf(m, fabsf(wr[j]));
    #pragma unroll
    for (int o = 16; o; o >>= 1) m = fmaxf(m, __shfl_xor_sync(0xffffffffu, m, o));
    __shared__ float sm4[4];
    if ((tid & 31) == 0) sm4[tid >> 5] = m;
    __syncthreads();
    m = fmaxf(fmaxf(sm4[0], sm4[1]), fmaxf(sm4[2], sm4[3]));
    float s = fmaxf(m, 1e-20f), inv = 127.0f / s;
    if (tid == 0) sw[row] = s;
    for (int j = tid; j < K; j += 128) {
        int8_t hh, ll; isplit(wr[j], inv, hh, ll);
        h[(size_t)row * K + j] = hh;
        l[(size_t)row * K + j] = ll;
    }
}

// ---------------------------------------------------------------------------
// LayerNorm: block (128 thr) per token; int8-split output + per-row scale.
// ---------------------------------------------------------------------------
__global__ void ln_kernel(const float* __restrict__ x, const float* __restrict__ w,
                          const float* __restrict__ b, int8_t* __restrict__ oh,
                          int8_t* __restrict__ ol, float* __restrict__ sa) {
    int t = blockIdx.x;
    const float4* xr = (const float4*)(x + (size_t)t * CDIM);
    float4 v = xr[threadIdx.x];
    float s  = v.x + v.y + v.z + v.w;
    float s2 = v.x*v.x + v.y*v.y + v.z*v.z + v.w*v.w;
    #pragma unroll
    for (int o = 16; o; o >>= 1) {
        s  += __shfl_xor_sync(0xffffffffu, s,  o);
        s2 += __shfl_xor_sync(0xffffffffu, s2, o);
    }
    __shared__ float ss[4], ssq[4], smx[4];
    int wid = threadIdx.x >> 5, lane = threadIdx.x & 31;
    if (lane == 0) { ss[wid] = s; ssq[wid] = s2; }
    __syncthreads();
    s  = ss[0] + ss[1] + ss[2] + ss[3];
    s2 = ssq[0] + ssq[1] + ssq[2] + ssq[3];
    float mean = s * (1.0f / CDIM);
    float var  = s2 * (1.0f / CDIM) - mean * mean;
    float rstd = rsqrtf(var + 1e-5f);
    float4 wv = ((const float4*)w)[threadIdx.x];
    float4 bv = ((const float4*)b)[threadIdx.x];
    float o0 = (v.x - mean) * rstd * wv.x + bv.x;
    float o1 = (v.y - mean) * rstd * wv.y + bv.y;
    float o2 = (v.z - mean) * rstd * wv.z + bv.z;
    float o3 = (v.w - mean) * rstd * wv.w + bv.w;
    float mx = fmaxf(fmaxf(fabsf(o0), fabsf(o1)), fmaxf(fabsf(o2), fabsf(o3)));
    #pragma unroll
    for (int o = 16; o; o >>= 1) mx = fmaxf(mx, __shfl_xor_sync(0xffffffffu, mx, o));
    if (lane == 0) smx[wid] = mx;
    __syncthreads();
    mx = fmaxf(fmaxf(smx[0], smx[1]), fmaxf(smx[2], smx[3]));
    float sc = fmaxf(mx, 1e-20f), inv = 127.0f / sc;
    int8_t h0,l0,h1,l1,h2,l2,h3,l3;
    isplit(o0, inv, h0, l0); isplit(o1, inv, h1, l1);
    isplit(o2, inv, h2, l2); isplit(o3, inv, h3, l3);
    char4 hc; hc.x=h0; hc.y=h1; hc.z=h2; hc.w=h3;
    char4 lc; lc.x=l0; lc.y=l1; lc.z=l2; lc.w=l3;
    ((char4*)(oh + (size_t)t * CDIM))[threadIdx.x] = hc;
    ((char4*)(ol + (size_t)t * CDIM))[threadIdx.x] = lc;
    if (threadIdx.x == 0) sa[t] = sc;
}

// ---------------------------------------------------------------------------
// Split-int8 IMMA GEMM: C = A @ W^T with A,W each 2-plane int8.
// acc_hh and acc_cross in int32 (exact); C = sa*sw/16129*(hh + cross/254).
// CTA tile 128(M)x64(N), stage depth 64 int8, THREE-stage cp.async pipeline,
// 8 warps 4x2 (32x32 warp tile), __launch_bounds__(256,2) -> 2 CTAs/SM.
// EPI: 0 = qkv: q*8 -> fp32 C (stride CDIM); k/v -> int8-split planes
//          (Ch/Cl = K, Vh/Vl = V) with fixed scale S_KV
//      1 = bias + residual R -> fp32 C (guard m<M)
//      2 = bias + exact GELU -> int8-split (Ch, Cl) with fixed scale S_H
// ---------------------------------------------------------------------------
#define ROWB 80
#define AROWS 128
#define BROWS 64
#define APL (AROWS*ROWB)             /* 10240 */
#define BPL (BROWS*ROWB)             /* 5120 */
#define AHI_B 0
#define ALO_B APL
#define BHI_B (2*APL)
#define BLO_B (2*APL + BPL)
#define STAGE_B (2*APL + 2*BPL)      /* 30720 */
#define NSTG 3
#define SMEM_BYTES (NSTG*STAGE_B)    /* 92160 */

__device__ __forceinline__ void cp_async16(uint32_t dst, const void* src) {
    asm volatile("cp.async.cg.shared.global [%0], [%1], 16;\n" :: "r"(dst), "l"(src));
}
#define LDSM4(r0,r1,r2,r3,addr) \
    asm volatile("ldmatrix.sync.aligned.m8n8.x4.shared.b16 {%0,%1,%2,%3}, [%4];" \
                 : "=r"(r0),"=r"(r1),"=r"(r2),"=r"(r3) : "r"(addr))
#define MMA_S8(c, a, b) \
    asm volatile("mma.sync.aligned.m16n8k32.row.col.satfinite.s32.s8.s8.s32 " \
                 "{%0,%1,%2,%3}, {%4,%5,%6,%7}, {%8,%9}, {%0,%1,%2,%3};\n" \
                 : "+r"((c)[0]), "+r"((c)[1]), "+r"((c)[2]), "+r"((c)[3]) \
                 : "r"((a)[0]), "r"((a)[1]), "r"((a)[2]), "r"((a)[3]), \
                   "r"((b)[0]), "r"((b)[1]))

template<int EPI>
__global__ void __launch_bounds__(256, 2)
imma_gemm(const int8_t* __restrict__ Ah, const int8_t* __restrict__ Al,
          const int8_t* __restrict__ Wh, const int8_t* __restrict__ Wl,
          const float* __restrict__ Sa, float saFixed,
          const float* __restrict__ Sw,
          const float* __restrict__ bias, const float* __restrict__ R,
          float* __restrict__ C, int8_t* __restrict__ Ch, int8_t* __restrict__ Cl,
          int8_t* __restrict__ Vh, int8_t* __restrict__ Vl,
          int M, int N, int K) {
    extern __shared__ char sm[];
    uint32_t sb = (uint32_t)__cvta_generic_to_shared(sm);

    const int tid   = threadIdx.x;
    const int lane  = tid & 31;
    const int wid   = tid >> 5;
    const int wm    = wid >> 1;              // 0..3 -> 32-row strip
    const int wn    = wid & 1;               // 0..1 -> 32-col strip
    const int gid   = lane >> 2;
    const int tig   = lane & 3;
    const int mBase = blockIdx.x * 128;
    const int nBase = blockIdx.y * 64;
    const int nk    = K >> 6;                // stages of 64 int8

    // A loader: 2 chunks/thread; B loader: 1 chunk/thread
    const int lrow = tid >> 1;
    const int lcc  = (tid & 1) * 2;
    const int brow = tid >> 2;
    const int bch  = tid & 3;

    const int lg = lane >> 3;
    const int lr = lane & 7;
    const int arow = lr + (lg & 1) * 8;
    const int akof = (lg >> 1) * 16;

    int acc_h[2][4][4], acc_x[2][4][4];
    #pragma unroll
    for (int mi = 0; mi < 2; mi++)
        #pragma unroll
        for (int ni = 0; ni < 4; ni++)
            #pragma unroll
            for (int c = 0; c < 4; c++) { acc_h[mi][ni][c] = 0; acc_x[mi][ni][c] = 0; }

    auto stage_load = [&](int kt, int st) {
        int k0 = kt * 64;
        size_t ga = (size_t)(mBase + lrow) * K + k0 + lcc * 16;
        size_t gb = (size_t)(nBase + brow) * K + k0 + bch * 16;
        uint32_t da = sb + st * STAGE_B + lrow * ROWB + lcc * 16;
        uint32_t db = sb + st * STAGE_B + brow * ROWB + bch * 16;
        cp_async16(da + AHI_B,      Ah + ga);
        cp_async16(da + AHI_B + 16, Ah + ga + 16);
        cp_async16(da + ALO_B,      Al + ga);
        cp_async16(da + ALO_B + 16, Al + ga + 16);
        cp_async16(db + BHI_B,      Wh + gb);
        cp_async16(db + BLO_B,      Wl + gb);
        asm volatile("cp.async.commit_group;\n");
    };

    stage_load(0, 0);
    stage_load(1, 1);

    for (int kt = 0; kt < nk; kt++) {
        if (kt + 2 < nk) {
            stage_load(kt + 2, (kt + 2) % NSTG);
            asm volatile("cp.async.wait_group 2;\n");
        } else if (kt + 1 < nk) {
            asm volatile("cp.async.wait_group 1;\n");
        } else {
            asm volatile("cp.async.wait_group 0;\n");
        }
        __syncthreads();

        uint32_t stb = sb + (kt % NSTG) * STAGE_B;

        #pragma unroll
        for (int k32 = 0; k32 < 2; k32++) {
            uint32_t kb = k32 * 32 + akof;

            // phase 1: hh
            uint32_t ah[2][4], bh[4][2];
            #pragma unroll
            for (int mi = 0; mi < 2; mi++) {
                uint32_t ra = stb + (uint32_t)(wm * 32 + mi * 16 + arow) * ROWB + kb;
                LDSM4(ah[mi][0], ah[mi][1], ah[mi][2], ah[mi][3], ra + AHI_B);
            }
            #pragma unroll
            for (int nn = 0; nn < 2; nn++) {
                uint32_t rb = stb + (uint32_t)(wn * 32 + nn * 16 + arow) * ROWB + kb;
                uint32_t r0, r1, r2, r3;
                LDSM4(r0, r1, r2, r3, rb + BHI_B);
                bh[2*nn][0] = r0; bh[2*nn][1] = r2;
                bh[2*nn+1][0] = r1; bh[2*nn+1][1] = r3;
            }
            #pragma unroll
            for (int mi = 0; mi < 2; mi++)
                #pragma unroll
                for (int ni = 0; ni < 4; ni++)
                    MMA_S8(acc_h[mi][ni], ah[mi], bh[ni]);

            // phase 2: h * l'
            {
                uint32_t bl[4][2];
                #pragma unroll
                for (int nn = 0; nn < 2; nn++) {
                    uint32_t rb = stb + (uint32_t)(wn * 32 + nn * 16 + arow) * ROWB + kb;
                    uint32_t r0, r1, r2, r3;
                    LDSM4(r0, r1, r2, r3, rb + BLO_B);
                    bl[2*nn][0] = r0; bl[2*nn][1] = r2;
                    bl[2*nn+1][0] = r1; bl[2*nn+1][1] = r3;
                }
                #pragma unroll
                for (int mi = 0; mi < 2; mi++)
                    #pragma unroll
                    for (int ni = 0; ni < 4; ni++)
                        MMA_S8(acc_x[mi][ni], ah[mi], bl[ni]);
            }

            // phase 3: l * h'
            {
                uint32_t al[2][4];
                #pragma unroll
                for (int mi = 0; mi < 2; mi++) {
                    uint32_t ra = stb + (uint32_t)(wm * 32 + mi * 16 + arow) * ROWB + kb;
                    LDSM4(al[mi][0], al[mi][1], al[mi][2], al[mi][3], ra + ALO_B);
                }
                #pragma unroll
                for (int mi = 0; mi < 2; mi++)
                    #pragma unroll
                    for (int ni = 0; ni < 4; ni++)
                        MMA_S8(acc_x[mi][ni], al[mi], bh[ni]);
            }
        }
        __syncthreads();
    }

    // epilogue
    const float inv16129 = 1.0f / 16129.0f;
    const float inv254   = 1.0f / 254.0f;
    const float invSH    = 127.0f / S_H;
    const float invSKV   = 127.0f / S_KV;
    #pragma unroll
    for (int mi = 0; mi < 2; mi++) {
        #pragma unroll
        for (int ni = 0; ni < 4; ni++) {
            int cn = nBase + wn * 32 + ni * 8 + 2 * tig;
            float f0 = Sw[cn]     * inv16129;
            float f1 = Sw[cn + 1] * inv16129;
            float b0 = bias[cn], b1 = bias[cn + 1];
            #pragma unroll
            for (int half = 0; half < 2; half++) {
                int rm = mBase + wm * 32 + mi * 16 + gid + half * 8;
                float sa = Sa ? Sa[rm] : saFixed;
                float v0 = sa * f0 * ((float)acc_h[mi][ni][half*2]   + (float)acc_x[mi][ni][half*2]   * inv254) + b0;
                float v1 = sa * f1 * ((float)acc_h[mi][ni][half*2+1] + (float)acc_x[mi][ni][half*2+1] * inv254) + b1;
                if (EPI == 0) {
                    if (cn < CDIM) {                 // q (scaled), fp32, stride CDIM
                        *(float2*)&C[(size_t)rm * CDIM + cn] = make_float2(v0 * 8.0f, v1 * 8.0f);
                    } else if (cn < 2 * CDIM) {      // k -> int8 split planes
                        int col = cn - CDIM;
                        int8_t h0,l0,h1,l1;
                        isplit(v0, invSKV, h0, l0);
                        isplit(v1, invSKV, h1, l1);
                        char2 hc; hc.x = h0; hc.y = h1;
                        char2 lc; lc.x = l0; lc.y = l1;
                        *(char2*)&Ch[(size_t)rm * CDIM + col] = hc;
                        *(char2*)&Cl[(size_t)rm * CDIM + col] = lc;
                    } else {                         // v -> int8 split planes
                        int col = cn - 2 * CDIM;
                        int8_t h0,l0,h1,l1;
                        isplit(v0, invSKV, h0, l0);
                        isplit(v1, invSKV, h1, l1);
                        char2 hc; hc.x = h0; hc.y = h1;
                        char2 lc; lc.x = l0; lc.y = l1;
                        *(char2*)&Vh[(size_t)rm * CDIM + col] = hc;
                        *(char2*)&Vl[(size_t)rm * CDIM + col] = lc;
                    }
                } else if (EPI == 1) {
                    if (rm < M) {
                        float2 r = *(const float2*)&R[(size_t)rm * N + cn];
                        *(float2*)&C[(size_t)rm * N + cn] = make_float2(v0 + r.x, v1 + r.y);
                    }
                } else {
                    v0 = 0.5f * v0 * (1.0f + erff(v0 * 0.70710678118654752f));
                    v1 = 0.5f * v1 * (1.0f + erff(v1 * 0.70710678118654752f));
                    int8_t h0,l0,h1,l1;
                    isplit(v0, invSH, h0, l0);
                    isplit(v1, invSH, h1, l1);
                    char2 hc; hc.x = h0; hc.y = h1;
                    char2 lc; lc.x = l0; lc.y = l1;
                    *(char2*)&Ch[(size_t)rm * N + cn] = hc;
                    *(char2*)&Cl[(size_t)rm * N + cn] = lc;
                }
            }
        }
    }
}

// ---------------------------------------------------------------------------
// Neighbor attention: block per token, warp = head, lane = 2 channels.
// q fp32 (pre-scaled); K/V from int8-split planes (fixed scale S_KV).
// Output int8-split + per-row scale (feeds proj GEMM).
// ---------------------------------------------------------------------------
__global__ void attn_kernel(const float* __restrict__ q_buf,
                            const int8_t* __restrict__ kh, const int8_t* __restrict__ kl,
                            const int8_t* __restrict__ vh, const int8_t* __restrict__ vl,
                            const int* __restrict__ which, const int* __restrict__ mask,
                            int8_t* __restrict__ yh, int8_t* __restrict__ yl,
                            float* __restrict__ sa) {
    int t = blockIdx.x;
    int n = t / DEPTH, d = t % DEPTH;
    int h = threadIdx.x >> 5;
    int lane = threadIdx.x & 31;

    const float c1 = S_KV / 127.0f;
    const float c2 = S_KV / (127.0f * 254.0f);

    float2 q = ((const float2*)(q_buf + (size_t)t * CDIM + h * HD))[lane];

    float sc[KNB];
    float2 vv[KNB];
    #pragma unroll
    for (int k = 0; k < KNB; k++) {
        int nb = which[n * KNB + k];
        size_t off = (size_t)(nb * DEPTH + d) * CDIM + h * HD + 2 * lane;
        char2 khc = *(const char2*)&kh[off];
        char2 klc = *(const char2*)&kl[off];
        float kx = c1 * (float)khc.x + c2 * (float)klc.x;
        float ky = c1 * (float)khc.y + c2 * (float)klc.y;
        char2 vhc = *(const char2*)&vh[off];
        char2 vlc = *(const char2*)&vl[off];
        vv[k].x = c1 * (float)vhc.x + c2 * (float)vlc.x;
        vv[k].y = c1 * (float)vhc.y + c2 * (float)vlc.y;
        float dot = q.x * kx + q.y * ky;
        #pragma unroll
        for (int o = 16; o; o >>= 1) dot += __shfl_xor_sync(0xffffffffu, dot, o);
        sc[k] = (mask[n * KNB + k] > 0) ? dot : -1.0e9f;
    }

    float mx = sc[0];
    #pragma unroll
    for (int k = 1; k < KNB; k++) mx = fmaxf(mx, sc[k]);
    float wsum = 0.0f, w[KNB];
    #pragma unroll
    for (int k = 0; k < KNB; k++) { w[k] = __expf(sc[k] - mx); wsum += w[k]; }
    float inv = 1.0f / wsum;

    float2 acc = make_float2(0.0f, 0.0f);
    #pragma unroll
    for (int k = 0; k < KNB; k++) {
        acc.x += w[k] * vv[k].x;
        acc.y += w[k] * vv[k].y;
    }
    acc.x *= inv; acc.y *= inv;

    float m = fmaxf(fabsf(acc.x), fabsf(acc.y));
    #pragma unroll
    for (int o = 16; o; o >>= 1) m = fmaxf(m, __shfl_xor_sync(0xffffffffu, m, o));
    __shared__ float am[8];
    if (lane == 0) am[h] = m;
    __syncthreads();
    m = am[0];
    #pragma unroll
    for (int i = 1; i < 8; i++) m = fmaxf(m, am[i]);
    float s = fmaxf(m, 1e-20f), qinv = 127.0f / s;

    int8_t h0,l0,h1,l1;
    isplit(acc.x, qinv, h0, l0);
    isplit(acc.y, qinv, h1, l1);
    char2 hc; hc.x = h0; hc.y = h1;
    char2 lc; lc.x = l0; lc.y = l1;
    *(char2*)&yh[(size_t)t * CDIM + h * HD + 2 * lane] = hc;
    *(char2*)&yl[(size_t)t * CDIM + h * HD + 2 * lane] = lc;
    if (threadIdx.x == 0) sa[t] = s;
}

// ---------------------------------------------------------------------------
extern "C" void kernel_launch(void* const* d_in, const int* in_sizes, int n_in,
                              void* d_out, int out_size) {
    const float* x      = (const float*)d_in[0];
    const int*   which  = (const int*)  d_in[1];
    const int*   mask   = (const int*)  d_in[2];
    const float* ln1_w  = (const float*)d_in[3];
    const float* ln1_b  = (const float*)d_in[4];
    const float* qkv_w  = (const float*)d_in[5];
    const float* qkv_b  = (const float*)d_in[6];
    const float* proj_w = (const float*)d_in[7];
    const float* proj_b = (const float*)d_in[8];
    const float* ln2_w  = (const float*)d_in[9];
    const float* ln2_b  = (const float*)d_in[10];
    const float* fc1_w  = (const float*)d_in[11];
    const float* fc1_b  = (const float*)d_in[12];
    const float* fc2_w  = (const float*)d_in[13];
    const float* fc2_b  = (const float*)d_in[14];
    float* out = (float*)d_out;

    float *p_q, *p_x2, *p_sa1, *p_sa2;
    int8_t *p_xnh, *p_xnl, *p_kh, *p_kl, *p_vh, *p_vl, *p_yh, *p_yl, *p_hh, *p_hl;
    int8_t *p_wqh, *p_wql, *p_wph, *p_wpl, *p_w1h, *p_w1l, *p_w2h, *p_w2l;
    float *p_swq, *p_swp, *p_sw1, *p_sw2;
    cudaGetSymbolAddress((void**)&p_q,   g_q);
    cudaGetSymbolAddress((void**)&p_x2,  g_x2);
    cudaGetSymbolAddress((void**)&p_sa1, g_sa1);
    cudaGetSymbolAddress((void**)&p_sa2, g_sa2);
    cudaGetSymbolAddress((void**)&p_xnh, g_xn_h);
    cudaGetSymbolAddress((void**)&p_xnl, g_xn_l);
    cudaGetSymbolAddress((void**)&p_kh,  g_k_h);
    cudaGetSymbolAddress((void**)&p_kl,  g_k_l);
    cudaGetSymbolAddress((void**)&p_vh,  g_v_h);
    cudaGetSymbolAddress((void**)&p_vl,  g_v_l);
    cudaGetSymbolAddress((void**)&p_yh,  g_y_h);
    cudaGetSymbolAddress((void**)&p_yl,  g_y_l);
    cudaGetSymbolAddress((void**)&p_hh,  g_h_h);
    cudaGetSymbolAddress((void**)&p_hl,  g_h_l);
    cudaGetSymbolAddress((void**)&p_wqh, g_wqkv_h);
    cudaGetSymbolAddress((void**)&p_wql, g_wqkv_l);
    cudaGetSymbolAddress((void**)&p_wph, g_wproj_h);
    cudaGetSymbolAddress((void**)&p_wpl, g_wproj_l);
    cudaGetSymbolAddress((void**)&p_w1h, g_wfc1_h);
    cudaGetSymbolAddress((void**)&p_w1l, g_wfc1_l);
    cudaGetSymbolAddress((void**)&p_w2h, g_wfc2_h);
    cudaGetSymbolAddress((void**)&p_w2l, g_wfc2_l);
    cudaGetSymbolAddress((void**)&p_swq, g_swqkv);
    cudaGetSymbolAddress((void**)&p_swp, g_swproj);
    cudaGetSymbolAddress((void**)&p_sw1, g_swfc1);
    cudaGetSymbolAddress((void**)&p_sw2, g_swfc2);

    cudaFuncSetAttribute(imma_gemm<0>, cudaFuncAttributeMaxDynamicSharedMemorySize, SMEM_BYTES);
    cudaFuncSetAttribute(imma_gemm<1>, cudaFuncAttributeMaxDynamicSharedMemorySize, SMEM_BYTES);
    cudaFuncSetAttribute(imma_gemm<2>, cudaFuncAttributeMaxDynamicSharedMemorySize, SMEM_BYTES);

    // weight quantization (per output row)
    wq_kernel<<<3*CDIM, 128>>>(qkv_w,  p_wqh, p_wql, p_swq, CDIM);
    wq_kernel<<<CDIM,   128>>>(proj_w, p_wph, p_wpl, p_swp, CDIM);
    wq_kernel<<<HIDD,   128>>>(fc1_w,  p_w1h, p_w1l, p_sw1, CDIM);
    wq_kernel<<<CDIM,   128>>>(fc2_w,  p_w2h, p_w2l, p_sw2, HIDD);

    // 1. LN1 -> int8 xn + sa1
    ln_kernel<<<MTOK, 128>>>(x, ln1_w, ln1_b, p_xnh, p_xnl, p_sa1);
    // 2. QKV GEMM -> q fp32 (x8), K/V int8-split planes
    imma_gemm<0><<<dim3(MT, 24), 256, SMEM_BYTES>>>(p_xnh, p_xnl, p_wqh, p_wql,
                                                    p_sa1, 0.0f, p_swq, qkv_b,
                                                    nullptr, p_q, p_kh, p_kl, p_vh, p_vl,
                                                    MTOK, 3 * CDIM, CDIM);
    // 3. attention -> int8 y + sa2
    attn_kernel<<<MTOK, 256>>>(p_q, p_kh, p_kl, p_vh, p_vl, which, mask,
                               p_yh, p_yl, p_sa2);
    // 4. proj + residual(x) -> fp32 x2
    imma_gemm<1><<<dim3(MT, 8), 256, SMEM_BYTES>>>(p_yh, p_yl, p_wph, p_wpl,
                                                   p_sa2, 0.0f, p_swp, proj_b,
                                                   x, p_x2, nullptr, nullptr, nullptr, nullptr,
                                                   MTOK, CDIM, CDIM);
    // 5. LN2 -> int8 xn + sa1
    ln_kernel<<<MTOK, 128>>>(p_x2, ln2_w, ln2_b, p_xnh, p_xnl, p_sa1);
    // 6. fc1 + GELU -> int8 h (fixed scale S_H)
    imma_gemm<2><<<dim3(MT, 32), 256, SMEM_BYTES>>>(p_xnh, p_xnl, p_w1h, p_w1l,
                                                    p_sa1, 0.0f, p_sw1, fc1_b,
                                                    nullptr, nullptr, p_hh, p_hl, nullptr, nullptr,
                                                    MTOK, HIDD, CDIM);
    // 7. fc2 + residual(x2) -> out  (A scale fixed = S_H)
    imma_gemm<1><<<dim3(MT, 8), 256, SMEM_BYTES>>>(p_hh, p_hl, p_w2h, p_w2l,
                                                   nullptr, S_H, p_sw2, fc2_b,
                                                   p_x2, out, nullptr, nullptr, nullptr, nullptr,
                                                   MTOK, CDIM, HIDD);
    (void)in_sizes; (void)n_in; (void)out_size;
}

// round 16
// speedup vs baseline: 1.0526x; 1.0526x over previous
#include <cuda_runtime.h>
#include <math.h>
#include <stdint.h>

#define NVERT 2562
#define DEPTH 8
#define CDIM  512
#define NHEAD 8
#define HD    64
#define KNB   8
#define HIDD  2048
#define MTOK  (NVERT*DEPTH)   /* 20496 */
#define MPAD  20608           /* 161*128 */
#define MT    161

// fp32 scratch
__device__ float g_qkv[(size_t)MPAD*3*CDIM];
__device__ float g_x2 [(size_t)MPAD*CDIM];
// int8 activation planes (hi, lo)
__device__ int8_t g_xn_h[(size_t)MPAD*CDIM];
__device__ int8_t g_xn_l[(size_t)MPAD*CDIM];
__device__ int8_t g_y_h [(size_t)MPAD*CDIM];
__device__ int8_t g_y_l [(size_t)MPAD*CDIM];
__device__ int8_t g_h_h [(size_t)MPAD*HIDD];
__device__ int8_t g_h_l [(size_t)MPAD*HIDD];
// per-row activation scales (zero-init -> padded rows contribute 0)
__device__ float g_sa1[MPAD];
__device__ float g_sa2[MPAD];
// int8 weight planes + per-row scales
__device__ int8_t g_wqkv_h[(size_t)3*CDIM*CDIM];
__device__ int8_t g_wqkv_l[(size_t)3*CDIM*CDIM];
__device__ int8_t g_wproj_h[(size_t)CDIM*CDIM];
__device__ int8_t g_wproj_l[(size_t)CDIM*CDIM];
__device__ int8_t g_wfc1_h[(size_t)HIDD*CDIM];
__device__ int8_t g_wfc1_l[(size_t)HIDD*CDIM];
__device__ int8_t g_wfc2_h[(size_t)CDIM*HIDD];
__device__ int8_t g_wfc2_l[(size_t)CDIM*HIDD];
__device__ float g_swqkv[3*CDIM];
__device__ float g_swproj[CDIM];
__device__ float g_swfc1[HIDD];
__device__ float g_swfc2[CDIM];

#define S_H 6.0f   /* fixed scale for GELU outputs */

// x ~= s/127 * (h + l/254)
__device__ __forceinline__ void isplit(float x, float inv /* =127/s */,
                                       int8_t& h, int8_t& l) {
    float q = fminf(fmaxf(x * inv, -127.0f), 127.0f);
    int hi = __float2int_rn(q);
    int lo = __float2int_rn((q - (float)hi) * 254.0f);
    h = (int8_t)hi; l = (int8_t)lo;
}

// ---------------------------------------------------------------------------
// Weight quantization: one block (128 thr) per output row; per-row scale.
// ---------------------------------------------------------------------------
__global__ void wq_kernel(const float* __restrict__ w, int8_t* __restrict__ h,
                          int8_t* __restrict__ l, float* __restrict__ sw, int K) {
    int row = blockIdx.x, tid = threadIdx.x;
    const float* wr = w + (size_t)row * K;
    float m = 0.0f;
    for (int j = tid; j < K; j += 128) m = fmaxf(m, fabsf(wr[j]));
    #pragma unroll
    for (int o = 16; o; o >>= 1) m = fmaxf(m, __shfl_xor_sync(0xffffffffu, m, o));
    __shared__ float sm4[4];
    if ((tid & 31) == 0) sm4[tid >> 5] = m;
    __syncthreads();
    m = fmaxf(fmaxf(sm4[0], sm4[1]), fmaxf(sm4[2], sm4[3]));
    float s = fmaxf(m, 1e-20f), inv = 127.0f / s;
    if (tid == 0) sw[row] = s;
    for (int j = tid; j < K; j += 128) {
        int8_t hh, ll; isplit(wr[j], inv, hh, ll);
        h[(size_t)row * K + j] = hh;
        l[(size_t)row * K + j] = ll;
    }
}

// ---------------------------------------------------------------------------
// LayerNorm: block (128 thr) per token; int8-split output + per-row scale.
// ---------------------------------------------------------------------------
__global__ void ln_kernel(const float* __restrict__ x, const float* __restrict__ w,
                          const float* __restrict__ b, int8_t* __restrict__ oh,
                          int8_t* __restrict__ ol, float* __restrict__ sa) {
    int t = blockIdx.x;
    const float4* xr = (const float4*)(x + (size_t)t * CDIM);
    float4 v = xr[threadIdx.x];
    float s  = v.x + v.y + v.z + v.w;
    float s2 = v.x*v.x + v.y*v.y + v.z*v.z + v.w*v.w;
    #pragma unroll
    for (int o = 16; o; o >>= 1) {
        s  += __shfl_xor_sync(0xffffffffu, s,  o);
        s2 += __shfl_xor_sync(0xffffffffu, s2, o);
    }
    __shared__ float ss[4], ssq[4], smx[4];
    int wid = threadIdx.x >> 5, lane = threadIdx.x & 31;
    if (lane == 0) { ss[wid] = s; ssq[wid] = s2; }
    __syncthreads();
    s  = ss[0] + ss[1] + ss[2] + ss[3];
    s2 = ssq[0] + ssq[1] + ssq[2] + ssq[3];
    float mean = s * (1.0f / CDIM);
    float var  = s2 * (1.0f / CDIM) - mean * mean;
    float rstd = rsqrtf(var + 1e-5f);
    float4 wv = ((const float4*)w)[threadIdx.x];
    float4 bv = ((const float4*)b)[threadIdx.x];
    float o0 = (v.x - mean) * rstd * wv.x + bv.x;
    float o1 = (v.y - mean) * rstd * wv.y + bv.y;
    float o2 = (v.z - mean) * rstd * wv.z + bv.z;
    float o3 = (v.w - mean) * rstd * wv.w + bv.w;
    float mx = fmaxf(fmaxf(fabsf(o0), fabsf(o1)), fmaxf(fabsf(o2), fabsf(o3)));
    #pragma unroll
    for (int o = 16; o; o >>= 1) mx = fmaxf(mx, __shfl_xor_sync(0xffffffffu, mx, o));
    if (lane == 0) smx[wid] = mx;
    __syncthreads();
    mx = fmaxf(fmaxf(smx[0], smx[1]), fmaxf(smx[2], smx[3]));
    float sc = fmaxf(mx, 1e-20f), inv = 127.0f / sc;
    int8_t h0,l0,h1,l1,h2,l2,h3,l3;
    isplit(o0, inv, h0, l0); isplit(o1, inv, h1, l1);
    isplit(o2, inv, h2, l2); isplit(o3, inv, h3, l3);
    char4 hc; hc.x=h0; hc.y=h1; hc.z=h2; hc.w=h3;
    char4 lc; lc.x=l0; lc.y=l1; lc.z=l2; lc.w=l3;
    ((char4*)(oh + (size_t)t * CDIM))[threadIdx.x] = hc;
    ((char4*)(ol + (size_t)t * CDIM))[threadIdx.x] = lc;
    if (threadIdx.x == 0) sa[t] = sc;
}

// ---------------------------------------------------------------------------
// Split-int8 IMMA GEMM: C = A @ W^T with A,W each 2-plane int8.
// acc_hh and acc_cross in int32 (exact); C = sa*sw/16129*(hh + cross/254).
// CTA tile 128(M)x64(N), stage depth 64 int8, THREE-stage cp.async pipeline,
// 8 warps 4x2 (32x32 warp tile), __launch_bounds__(256,2) -> 2 CTAs/SM.
// EPI: 0 = bias + q-scale -> fp32 C
//      1 = bias + residual R -> fp32 C (guard m<M)
//      2 = bias + exact GELU -> int8-split (Ch, Cl) with fixed scale S_H
// ---------------------------------------------------------------------------
#define ROWB 80
#define AROWS 128
#define BROWS 64
#define APL (AROWS*ROWB)             /* 10240 */
#define BPL (BROWS*ROWB)             /* 5120 */
#define AHI_B 0
#define ALO_B APL
#define BHI_B (2*APL)
#define BLO_B (2*APL + BPL)
#define STAGE_B (2*APL + 2*BPL)      /* 30720 */
#define NSTG 3
#define SMEM_BYTES (NSTG*STAGE_B)    /* 92160 */

__device__ __forceinline__ void cp_async16(uint32_t dst, const void* src) {
    asm volatile("cp.async.cg.shared.global [%0], [%1], 16;\n" :: "r"(dst), "l"(src));
}
#define LDSM4(r0,r1,r2,r3,addr) \
    asm volatile("ldmatrix.sync.aligned.m8n8.x4.shared.b16 {%0,%1,%2,%3}, [%4];" \
                 : "=r"(r0),"=r"(r1),"=r"(r2),"=r"(r3) : "r"(addr))
#define MMA_S8(c, a, b) \
    asm volatile("mma.sync.aligned.m16n8k32.row.col.satfinite.s32.s8.s8.s32 " \
                 "{%0,%1,%2,%3}, {%4,%5,%6,%7}, {%8,%9}, {%0,%1,%2,%3};\n" \
                 : "+r"((c)[0]), "+r"((c)[1]), "+r"((c)[2]), "+r"((c)[3]) \
                 : "r"((a)[0]), "r"((a)[1]), "r"((a)[2]), "r"((a)[3]), \
                   "r"((b)[0]), "r"((b)[1]))

template<int EPI>
__global__ void __launch_bounds__(256, 2)
imma_gemm(const int8_t* __restrict__ Ah, const int8_t* __restrict__ Al,
          const int8_t* __restrict__ Wh, const int8_t* __restrict__ Wl,
          const float* __restrict__ Sa, float saFixed,
          const float* __restrict__ Sw,
          const float* __restrict__ bias, const float* __restrict__ R,
          float* __restrict__ C, int8_t* __restrict__ Ch, int8_t* __restrict__ Cl,
          int M, int N, int K) {
    extern __shared__ char sm[];
    uint32_t sb = (uint32_t)__cvta_generic_to_shared(sm);

    const int tid   = threadIdx.x;
    const int lane  = tid & 31;
    const int wid   = tid >> 5;
    const int wm    = wid >> 1;              // 0..3 -> 32-row strip
    const int wn    = wid & 1;               // 0..1 -> 32-col strip
    const int gid   = lane >> 2;
    const int tig   = lane & 3;
    const int mBase = blockIdx.x * 128;
    const int nBase = blockIdx.y * 64;
    const int nk    = K >> 6;                // stages of 64 int8

    // A loader: 2 chunks/thread; B loader: 1 chunk/thread
    const int lrow = tid >> 1;
    const int lcc  = (tid & 1) * 2;
    const int brow = tid >> 2;
    const int bch  = tid & 3;

    const int lg = lane >> 3;
    const int lr = lane & 7;
    const int arow = lr + (lg & 1) * 8;
    const int akof = (lg >> 1) * 16;

    int acc_h[2][4][4], acc_x[2][4][4];
    #pragma unroll
    for (int mi = 0; mi < 2; mi++)
        #pragma unroll
        for (int ni = 0; ni < 4; ni++)
            #pragma unroll
            for (int c = 0; c < 4; c++) { acc_h[mi][ni][c] = 0; acc_x[mi][ni][c] = 0; }

    auto stage_load = [&](int kt, int st) {
        int k0 = kt * 64;
        size_t ga = (size_t)(mBase + lrow) * K + k0 + lcc * 16;
        size_t gb = (size_t)(nBase + brow) * K + k0 + bch * 16;
        uint32_t da = sb + st * STAGE_B + lrow * ROWB + lcc * 16;
        uint32_t db = sb + st * STAGE_B + brow * ROWB + bch * 16;
        cp_async16(da + AHI_B,      Ah + ga);
        cp_async16(da + AHI_B + 16, Ah + ga + 16);
        cp_async16(da + ALO_B,      Al + ga);
        cp_async16(da + ALO_B + 16, Al + ga + 16);
        cp_async16(db + BHI_B,      Wh + gb);
        cp_async16(db + BLO_B,      Wl + gb);
        asm volatile("cp.async.commit_group;\n");
    };

    stage_load(0, 0);
    stage_load(1, 1);

    for (int kt = 0; kt < nk; kt++) {
        if (kt + 2 < nk) {
            stage_load(kt + 2, (kt + 2) % NSTG);
            asm volatile("cp.async.wait_group 2;\n");
        } else if (kt + 1 < nk) {
            asm volatile("cp.async.wait_group 1;\n");
        } else {
            asm volatile("cp.async.wait_group 0;\n");
        }
        __syncthreads();

        uint32_t stb = sb + (kt % NSTG) * STAGE_B;

        #pragma unroll
        for (int k32 = 0; k32 < 2; k32++) {
            uint32_t kb = k32 * 32 + akof;

            // phase 1: hh
            uint32_t ah[2][4], bh[4][2];
            #pragma unroll
            for (int mi = 0; mi < 2; mi++) {
                uint32_t ra = stb + (uint32_t)(wm * 32 + mi * 16 + arow) * ROWB + kb;
                LDSM4(ah[mi][0], ah[mi][1], ah[mi][2], ah[mi][3], ra + AHI_B);
            }
            #pragma unroll
            for (int nn = 0; nn < 2; nn++) {
                uint32_t rb = stb + (uint32_t)(wn * 32 + nn * 16 + arow) * ROWB + kb;
                uint32_t r0, r1, r2, r3;
                LDSM4(r0, r1, r2, r3, rb + BHI_B);
                bh[2*nn][0] = r0; bh[2*nn][1] = r2;
                bh[2*nn+1][0] = r1; bh[2*nn+1][1] = r3;
            }
            #pragma unroll
            for (int mi = 0; mi < 2; mi++)
                #pragma unroll
                for (int ni = 0; ni < 4; ni++)
                    MMA_S8(acc_h[mi][ni], ah[mi], bh[ni]);

            // phase 2: h * l'
            {
                uint32_t bl[4][2];
                #pragma unroll
                for (int nn = 0; nn < 2; nn++) {
                    uint32_t rb = stb + (uint32_t)(wn * 32 + nn * 16 + arow) * ROWB + kb;
                    uint32_t r0, r1, r2, r3;
                    LDSM4(r0, r1, r2, r3, rb + BLO_B);
                    bl[2*nn][0] = r0; bl[2*nn][1] = r2;
                    bl[2*nn+1][0] = r1; bl[2*nn+1][1] = r3;
                }
                #pragma unroll
                for (int mi = 0; mi < 2; mi++)
                    #pragma unroll
                    for (int ni = 0; ni < 4; ni++)
                        MMA_S8(acc_x[mi][ni], ah[mi], bl[ni]);
            }

            // phase 3: l * h'
            {
                uint32_t al[2][4];
                #pragma unroll
                for (int mi = 0; mi < 2; mi++) {
                    uint32_t ra = stb + (uint32_t)(wm * 32 + mi * 16 + arow) * ROWB + kb;
                    LDSM4(al[mi][0], al[mi][1], al[mi][2], al[mi][3], ra + ALO_B);
                }
                #pragma unroll
                for (int mi = 0; mi < 2; mi++)
                    #pragma unroll
                    for (int ni = 0; ni < 4; ni++)
                        MMA_S8(acc_x[mi][ni], al[mi], bh[ni]);
            }
        }
        __syncthreads();
    }

    // epilogue
    const float inv16129 = 1.0f / 16129.0f;
    const float inv254   = 1.0f / 254.0f;
    const float invSH    = 127.0f / S_H;
    #pragma unroll
    for (int mi = 0; mi < 2; mi++) {
        #pragma unroll
        for (int ni = 0; ni < 4; ni++) {
            int cn = nBase + wn * 32 + ni * 8 + 2 * tig;
            float f0 = Sw[cn]     * inv16129;
            float f1 = Sw[cn + 1] * inv16129;
            float b0 = bias[cn], b1 = bias[cn + 1];
            #pragma unroll
            for (int half = 0; half < 2; half++) {
                int rm = mBase + wm * 32 + mi * 16 + gid + half * 8;
                float sa = Sa ? Sa[rm] : saFixed;
                float v0 = sa * f0 * ((float)acc_h[mi][ni][half*2]   + (float)acc_x[mi][ni][half*2]   * inv254) + b0;
                float v1 = sa * f1 * ((float)acc_h[mi][ni][half*2+1] + (float)acc_x[mi][ni][half*2+1] * inv254) + b1;
                if (EPI == 0) {
                    if (cn < CDIM)     v0 *= 8.0f;
                    if (cn + 1 < CDIM) v1 *= 8.0f;
                    *(float2*)&C[(size_t)rm * N + cn] = make_float2(v0, v1);
                } else if (EPI == 1) {
                    if (rm < M) {
                        float2 r = *(const float2*)&R[(size_t)rm * N + cn];
                        *(float2*)&C[(size_t)rm * N + cn] = make_float2(v0 + r.x, v1 + r.y);
                    }
                } else {
                    v0 = 0.5f * v0 * (1.0f + erff(v0 * 0.70710678118654752f));
                    v1 = 0.5f * v1 * (1.0f + erff(v1 * 0.70710678118654752f));
                    int8_t h0,l0,h1,l1;
                    isplit(v0, invSH, h0, l0);
                    isplit(v1, invSH, h1, l1);
                    char2 hc; hc.x = h0; hc.y = h1;
                    char2 lc; lc.x = l0; lc.y = l1;
                    *(char2*)&Ch[(size_t)rm * N + cn] = hc;
                    *(char2*)&Cl[(size_t)rm * N + cn] = lc;
                }
            }
        }
    }
}

// ---------------------------------------------------------------------------
// Neighbor attention: block per token, warp = head, lane = 2 channels.
// Output int8-split + per-row scale (feeds proj GEMM).
// ---------------------------------------------------------------------------
__global__ void attn_kernel(const float* __restrict__ qkv, const int* __restrict__ which,
                            const int* __restrict__ mask, int8_t* __restrict__ yh,
                            int8_t* __restrict__ yl, float* __restrict__ sa) {
    int t = blockIdx.x;
    int n = t / DEPTH, d = t % DEPTH;
    int h = threadIdx.x >> 5;
    int lane = threadIdx.x & 31;

    float2 q = ((const float2*)(qkv + (size_t)t * (3 * CDIM) + h * HD))[lane];

    float sc[KNB];
    float2 vv[KNB];
    #pragma unroll
    for (int k = 0; k < KNB; k++) {
        int nb = which[n * KNB + k];
        const float* base = qkv + (size_t)(nb * DEPTH + d) * (3 * CDIM) + h * HD;
        float2 kv = ((const float2*)(base + CDIM))[lane];
        vv[k]     = ((const float2*)(base + 2 * CDIM))[lane];
        float dot = q.x * kv.x + q.y * kv.y;
        #pragma unroll
        for (int o = 16; o; o >>= 1) dot += __shfl_xor_sync(0xffffffffu, dot, o);
        sc[k] = (mask[n * KNB + k] > 0) ? dot : -1.0e9f;
    }

    float mx = sc[0];
    #pragma unroll
    for (int k = 1; k < KNB; k++) mx = fmaxf(mx, sc[k]);
    float wsum = 0.0f, w[KNB];
    #pragma unroll
    for (int k = 0; k < KNB; k++) { w[k] = __expf(sc[k] - mx); wsum += w[k]; }
    float inv = 1.0f / wsum;

    float2 acc = make_float2(0.0f, 0.0f);
    #pragma unroll
    for (int k = 0; k < KNB; k++) {
        acc.x += w[k] * vv[k].x;
        acc.y += w[k] * vv[k].y;
    }
    acc.x *= inv; acc.y *= inv;

    float m = fmaxf(fabsf(acc.x), fabsf(acc.y));
    #pragma unroll
    for (int o = 16; o; o >>= 1) m = fmaxf(m, __shfl_xor_sync(0xffffffffu, m, o));
    __shared__ float am[8];
    if (lane == 0) am[h] = m;
    __syncthreads();
    m = am[0];
    #pragma unroll
    for (int i = 1; i < 8; i++) m = fmaxf(m, am[i]);
    float s = fmaxf(m, 1e-20f), qinv = 127.0f / s;

    int8_t h0,l0,h1,l1;
    isplit(acc.x, qinv, h0, l0);
    isplit(acc.y, qinv, h1, l1);
    char2 hc; hc.x = h0; hc.y = h1;
    char2 lc; lc.x = l0; lc.y = l1;
    *(char2*)&yh[(size_t)t * CDIM + h * HD + 2 * lane] = hc;
    *(char2*)&yl[(size_t)t * CDIM + h * HD + 2 * lane] = lc;
    if (threadIdx.x == 0) sa[t] = s;
}

// ---------------------------------------------------------------------------
extern "C" void kernel_launch(void* const* d_in, const int* in_sizes, int n_in,
                              void* d_out, int out_size) {
    const float* x      = (const float*)d_in[0];
    const int*   which  = (const int*)  d_in[1];
    const int*   mask   = (const int*)  d_in[2];
    const float* ln1_w  = (const float*)d_in[3];
    const float* ln1_b  = (const float*)d_in[4];
    const float* qkv_w  = (const float*)d_in[5];
    const float* qkv_b  = (const float*)d_in[6];
    const float* proj_w = (const float*)d_in[7];
    const float* proj_b = (const float*)d_in[8];
    const float* ln2_w  = (const float*)d_in[9];
    const float* ln2_b  = (const float*)d_in[10];
    const float* fc1_w  = (const float*)d_in[11];
    const float* fc1_b  = (const float*)d_in[12];
    const float* fc2_w  = (const float*)d_in[13];
    const float* fc2_b  = (const float*)d_in[14];
    float* out = (float*)d_out;

    float *p_qkv, *p_x2, *p_sa1, *p_sa2;
    int8_t *p_xnh, *p_xnl, *p_yh, *p_yl, *p_hh, *p_hl;
    int8_t *p_wqh, *p_wql, *p_wph, *p_wpl, *p_w1h, *p_w1l, *p_w2h, *p_w2l;
    float *p_swq, *p_swp, *p_sw1, *p_sw2;
    cudaGetSymbolAddress((void**)&p_qkv, g_qkv);
    cudaGetSymbolAddress((void**)&p_x2,  g_x2);
    cudaGetSymbolAddress((void**)&p_sa1, g_sa1);
    cudaGetSymbolAddress((void**)&p_sa2, g_sa2);
    cudaGetSymbolAddress((void**)&p_xnh, g_xn_h);
    cudaGetSymbolAddress((void**)&p_xnl, g_xn_l);
    cudaGetSymbolAddress((void**)&p_yh,  g_y_h);
    cudaGetSymbolAddress((void**)&p_yl,  g_y_l);
    cudaGetSymbolAddress((void**)&p_hh,  g_h_h);
    cudaGetSymbolAddress((void**)&p_hl,  g_h_l);
    cudaGetSymbolAddress((void**)&p_wqh, g_wqkv_h);
    cudaGetSymbolAddress((void**)&p_wql, g_wqkv_l);
    cudaGetSymbolAddress((void**)&p_wph, g_wproj_h);
    cudaGetSymbolAddress((void**)&p_wpl, g_wproj_l);
    cudaGetSymbolAddress((void**)&p_w1h, g_wfc1_h);
    cudaGetSymbolAddress((void**)&p_w1l, g_wfc1_l);
    cudaGetSymbolAddress((void**)&p_w2h, g_wfc2_h);
    cudaGetSymbolAddress((void**)&p_w2l, g_wfc2_l);
    cudaGetSymbolAddress((void**)&p_swq, g_swqkv);
    cudaGetSymbolAddress((void**)&p_swp, g_swproj);
    cudaGetSymbolAddress((void**)&p_sw1, g_swfc1);
    cudaGetSymbolAddress((void**)&p_sw2, g_swfc2);

    cudaFuncSetAttribute(imma_gemm<0>, cudaFuncAttributeMaxDynamicSharedMemorySize, SMEM_BYTES);
    cudaFuncSetAttribute(imma_gemm<1>, cudaFuncAttributeMaxDynamicSharedMemorySize, SMEM_BYTES);
    cudaFuncSetAttribute(imma_gemm<2>, cudaFuncAttributeMaxDynamicSharedMemorySize, SMEM_BYTES);

    // weight quantization (per output row)
    wq_kernel<<<3*CDIM, 128>>>(qkv_w,  p_wqh, p_wql, p_swq, CDIM);
    wq_kernel<<<CDIM,   128>>>(proj_w, p_wph, p_wpl, p_swp, CDIM);
    wq_kernel<<<HIDD,   128>>>(fc1_w,  p_w1h, p_w1l, p_sw1, CDIM);
    wq_kernel<<<CDIM,   128>>>(fc2_w,  p_w2h, p_w2l, p_sw2, HIDD);

    // 1. LN1 -> int8 xn + sa1
    ln_kernel<<<MTOK, 128>>>(x, ln1_w, ln1_b, p_xnh, p_xnl, p_sa1);
    // 2. QKV GEMM (+ q scale) -> fp32 qkv   (N tiles of 64)
    imma_gemm<0><<<dim3(MT, 24), 256, SMEM_BYTES>>>(p_xnh, p_xnl, p_wqh, p_wql,
                                                    p_sa1, 0.0f, p_swq, qkv_b,
                                                    nullptr, p_qkv, nullptr, nullptr,
                                                    MTOK, 3 * CDIM, CDIM);
    // 3. attention -> int8 y + sa2
    attn_kernel<<<MTOK, 256>>>(p_qkv, which, mask, p_yh, p_yl, p_sa2);
    // 4. proj + residual(x) -> fp32 x2
    imma_gemm<1><<<dim3(MT, 8), 256, SMEM_BYTES>>>(p_yh, p_yl, p_wph, p_wpl,
                                                   p_sa2, 0.0f, p_swp, proj_b,
                                                   x, p_x2, nullptr, nullptr,
                                                   MTOK, CDIM, CDIM);
    // 5. LN2 -> int8 xn + sa1
    ln_kernel<<<MTOK, 128>>>(p_x2, ln2_w, ln2_b, p_xnh, p_xnl, p_sa1);
    // 6. fc1 + GELU -> int8 h (fixed scale S_H)
    imma_gemm<2><<<dim3(MT, 32), 256, SMEM_BYTES>>>(p_xnh, p_xnl, p_w1h, p_w1l,
                                                    p_sa1, 0.0f, p_sw1, fc1_b,
                                                    nullptr, nullptr, p_hh, p_hl,
                                                    MTOK, HIDD, CDIM);
    // 7. fc2 + residual(x2) -> out  (A scale fixed = S_H)
    imma_gemm<1><<<dim3(MT, 8), 256, SMEM_BYTES>>>(p_hh, p_hl, p_w2h, p_w2l,
                                                   nullptr, S_H, p_sw2, fc2_b,
                                                   p_x2, out, nullptr, nullptr,
                                                   MTOK, CDIM, HIDD);
    (void)in_sizes; (void)n_in; (void)out_size;
}

// round 17
// speedup vs baseline: 1.0825x; 1.0284x over previous
#include <cuda_runtime.h>
#include <math.h>
#include <stdint.h>

#define NVERT 2562
#define DEPTH 8
#define CDIM  512
#define NHEAD 8
#define HD    64
#define KNB   8
#define HIDD  2048
#define MTOK  (NVERT*DEPTH)   /* 20496 */
#define MPAD  20608           /* 161*128 */
#define MT    161

// fp32 scratch
__device__ float g_qkv[(size_t)MPAD*3*CDIM];
__device__ float g_x2 [(size_t)MPAD*CDIM];
// int8 activation planes (hi, lo)
__device__ int8_t g_xn_h[(size_t)MPAD*CDIM];
__device__ int8_t g_xn_l[(size_t)MPAD*CDIM];
__device__ int8_t g_y_h [(size_t)MPAD*CDIM];
__device__ int8_t g_y_l [(size_t)MPAD*CDIM];
__device__ int8_t g_h_h [(size_t)MPAD*HIDD];
__device__ int8_t g_h_l [(size_t)MPAD*HIDD];
// per-row activation scales (zero-init -> padded rows contribute 0)
__device__ float g_sa1[MPAD];
__device__ float g_sa2[MPAD];
// int8 weight planes + per-row scales
__device__ int8_t g_wqkv_h[(size_t)3*CDIM*CDIM];
__device__ int8_t g_wqkv_l[(size_t)3*CDIM*CDIM];
__device__ int8_t g_wproj_h[(size_t)CDIM*CDIM];
__device__ int8_t g_wproj_l[(size_t)CDIM*CDIM];
__device__ int8_t g_wfc1_h[(size_t)HIDD*CDIM];
__device__ int8_t g_wfc1_l[(size_t)HIDD*CDIM];
__device__ int8_t g_wfc2_h[(size_t)CDIM*HIDD];
__device__ int8_t g_wfc2_l[(size_t)CDIM*HIDD];
__device__ float g_swqkv[3*CDIM];
__device__ float g_swproj[CDIM];
__device__ float g_swfc1[HIDD];
__device__ float g_swfc2[CDIM];

#define S_H 6.0f   /* fixed scale for GELU outputs */

// x ~= s/127 * (h + l/254)
__device__ __forceinline__ void isplit(float x, float inv /* =127/s */,
                                       int8_t& h, int8_t& l) {
    float q = fminf(fmaxf(x * inv, -127.0f), 127.0f);
    int hi = __float2int_rn(q);
    int lo = __float2int_rn((q - (float)hi) * 254.0f);
    h = (int8_t)hi; l = (int8_t)lo;
}

// ---------------------------------------------------------------------------
// Weight quantization: one block (128 thr) per output row; per-row scale.
// ---------------------------------------------------------------------------
__global__ void wq_kernel(const float* __restrict__ w, int8_t* __restrict__ h,
                          int8_t* __restrict__ l, float* __restrict__ sw, int K) {
    int row = blockIdx.x, tid = threadIdx.x;
    const float* wr = w + (size_t)row * K;
    float m = 0.0f;
    for (int j = tid; j < K; j += 128) m = fmaxf(m, fabsf(wr[j]));
    #pragma unroll
    for (int o = 16; o; o >>= 1) m = fmaxf(m, __shfl_xor_sync(0xffffffffu, m, o));
    __shared__ float sm4[4];
    if ((tid & 31) == 0) sm4[tid >> 5] = m;
    __syncthreads();
    m = fmaxf(fmaxf(sm4[0], sm4[1]), fmaxf(sm4[2], sm4[3]));
    float s = fmaxf(m, 1e-20f), inv = 127.0f / s;
    if (tid == 0) sw[row] = s;
    for (int j = tid; j < K; j += 128) {
        int8_t hh, ll; isplit(wr[j], inv, hh, ll);
        h[(size_t)row * K + j] = hh;
        l[(size_t)row * K + j] = ll;
    }
}

// ---------------------------------------------------------------------------
// LayerNorm: block (128 thr) per token; int8-split output + per-row scale.
// ---------------------------------------------------------------------------
__global__ void ln_kernel(const float* __restrict__ x, const float* __restrict__ w,
                          const float* __restrict__ b, int8_t* __restrict__ oh,
                          int8_t* __restrict__ ol, float* __restrict__ sa) {
    int t = blockIdx.x;
    const float4* xr = (const float4*)(x + (size_t)t * CDIM);
    float4 v = xr[threadIdx.x];
    float s  = v.x + v.y + v.z + v.w;
    float s2 = v.x*v.x + v.y*v.y + v.z*v.z + v.w*v.w;
    #pragma unroll
    for (int o = 16; o; o >>= 1) {
        s  += __shfl_xor_sync(0xffffffffu, s,  o);
        s2 += __shfl_xor_sync(0xffffffffu, s2, o);
    }
    __shared__ float ss[4], ssq[4], smx[4];
    int wid = threadIdx.x >> 5, lane = threadIdx.x & 31;
    if (lane == 0) { ss[wid] = s; ssq[wid] = s2; }
    __syncthreads();
    s  = ss[0] + ss[1] + ss[2] + ss[3];
    s2 = ssq[0] + ssq[1] + ssq[2] + ssq[3];
    float mean = s * (1.0f / CDIM);
    float var  = s2 * (1.0f / CDIM) - mean * mean;
    float rstd = rsqrtf(var + 1e-5f);
    float4 wv = ((const float4*)w)[threadIdx.x];
    float4 bv = ((const float4*)b)[threadIdx.x];
    float o0 = (v.x - mean) * rstd * wv.x + bv.x;
    float o1 = (v.y - mean) * rstd * wv.y + bv.y;
    float o2 = (v.z - mean) * rstd * wv.z + bv.z;
    float o3 = (v.w - mean) * rstd * wv.w + bv.w;
    float mx = fmaxf(fmaxf(fabsf(o0), fabsf(o1)), fmaxf(fabsf(o2), fabsf(o3)));
    #pragma unroll
    for (int o = 16; o; o >>= 1) mx = fmaxf(mx, __shfl_xor_sync(0xffffffffu, mx, o));
    if (lane == 0) smx[wid] = mx;
    __syncthreads();
    mx = fmaxf(fmaxf(smx[0], smx[1]), fmaxf(smx[2], smx[3]));
    float sc = fmaxf(mx, 1e-20f), inv = 127.0f / sc;
    int8_t h0,l0,h1,l1,h2,l2,h3,l3;
    isplit(o0, inv, h0, l0); isplit(o1, inv, h1, l1);
    isplit(o2, inv, h2, l2); isplit(o3, inv, h3, l3);
    char4 hc; hc.x=h0; hc.y=h1; hc.z=h2; hc.w=h3;
    char4 lc; lc.x=l0; lc.y=l1; lc.z=l2; lc.w=l3;
    ((char4*)(oh + (size_t)t * CDIM))[threadIdx.x] = hc;
    ((char4*)(ol + (size_t)t * CDIM))[threadIdx.x] = lc;
    if (threadIdx.x == 0) sa[t] = sc;
}

// ---------------------------------------------------------------------------
// Split-int8 IMMA GEMM: C = A @ W^T with A,W each 2-plane int8.
// acc_hh and acc_cross in int32 (exact); C = sa*sw/16129*(hh + cross/254).
// CTA tile 128(M)x64(N), stage depth 64 int8, double-buffered cp.async,
// 8 warps 4x2 (32x32 warp tile), __launch_bounds__(256,2) -> 2 CTAs/SM.
// EPI: 0 = bias + q-scale -> fp32 C
//      1 = bias + residual R -> fp32 C (guard m<M)
//      2 = bias + exact GELU -> int8-split (Ch, Cl) with fixed scale S_H
// ---------------------------------------------------------------------------
#define ROWB 80
#define AROWS 128
#define BROWS 64
#define APL (AROWS*ROWB)             /* 10240 */
#define BPL (BROWS*ROWB)             /* 5120 */
#define AHI_B 0
#define ALO_B APL
#define BHI_B (2*APL)
#define BLO_B (2*APL + BPL)
#define STAGE_B (2*APL + 2*BPL)      /* 30720 */
#define SMEM_BYTES (2*STAGE_B)       /* 61440 */

__device__ __forceinline__ void cp_async16(uint32_t dst, const void* src) {
    asm volatile("cp.async.cg.shared.global [%0], [%1], 16;\n" :: "r"(dst), "l"(src));
}
#define LDSM4(r0,r1,r2,r3,addr) \
    asm volatile("ldmatrix.sync.aligned.m8n8.x4.shared.b16 {%0,%1,%2,%3}, [%4];" \
                 : "=r"(r0),"=r"(r1),"=r"(r2),"=r"(r3) : "r"(addr))
#define MMA_S8(c, a, b) \
    asm volatile("mma.sync.aligned.m16n8k32.row.col.satfinite.s32.s8.s8.s32 " \
                 "{%0,%1,%2,%3}, {%4,%5,%6,%7}, {%8,%9}, {%0,%1,%2,%3};\n" \
                 : "+r"((c)[0]), "+r"((c)[1]), "+r"((c)[2]), "+r"((c)[3]) \
                 : "r"((a)[0]), "r"((a)[1]), "r"((a)[2]), "r"((a)[3]), \
                   "r"((b)[0]), "r"((b)[1]))

template<int EPI>
__global__ void __launch_bounds__(256, 2)
imma_gemm(const int8_t* __restrict__ Ah, const int8_t* __restrict__ Al,
          const int8_t* __restrict__ Wh, const int8_t* __restrict__ Wl,
          const float* __restrict__ Sa, float saFixed,
          const float* __restrict__ Sw,
          const float* __restrict__ bias, const float* __restrict__ R,
          float* __restrict__ C, int8_t* __restrict__ Ch, int8_t* __restrict__ Cl,
          int M, int N, int K) {
    extern __shared__ char sm[];
    uint32_t sb = (uint32_t)__cvta_generic_to_shared(sm);

    const int tid   = threadIdx.x;
    const int lane  = tid & 31;
    const int wid   = tid >> 5;
    const int wm    = wid >> 1;              // 0..3 -> 32-row strip
    const int wn    = wid & 1;               // 0..1 -> 32-col strip
    const int gid   = lane >> 2;
    const int tig   = lane & 3;
    const int mBase = blockIdx.x * 128;
    const int nBase = blockIdx.y * 64;
    const int nk    = K >> 6;                // stages of 64 int8

    // A loader: 2 chunks/thread; B loader: 1 chunk/thread
    const int lrow = tid >> 1;
    const int lcc  = (tid & 1) * 2;
    const int brow = tid >> 2;
    const int bch  = tid & 3;

    const int lg = lane >> 3;
    const int lr = lane & 7;
    const int arow = lr + (lg & 1) * 8;
    const int akof = (lg >> 1) * 16;

    int acc_h[2][4][4], acc_x[2][4][4];
    #pragma unroll
    for (int mi = 0; mi < 2; mi++)
        #pragma unroll
        for (int ni = 0; ni < 4; ni++)
            #pragma unroll
            for (int c = 0; c < 4; c++) { acc_h[mi][ni][c] = 0; acc_x[mi][ni][c] = 0; }

    auto stage_load = [&](int kt, int st) {
        int k0 = kt * 64;
        size_t ga = (size_t)(mBase + lrow) * K + k0 + lcc * 16;
        size_t gb = (size_t)(nBase + brow) * K + k0 + bch * 16;
        uint32_t da = sb + st * STAGE_B + lrow * ROWB + lcc * 16;
        uint32_t db = sb + st * STAGE_B + brow * ROWB + bch * 16;
        cp_async16(da + AHI_B,      Ah + ga);
        cp_async16(da + AHI_B + 16, Ah + ga + 16);
        cp_async16(da + ALO_B,      Al + ga);
        cp_async16(da + ALO_B + 16, Al + ga + 16);
        cp_async16(db + BHI_B,      Wh + gb);
        cp_async16(db + BLO_B,      Wl + gb);
        asm volatile("cp.async.commit_group;\n");
    };

    stage_load(0, 0);

    for (int kt = 0; kt < nk; kt++) {
        int st = kt & 1;
        if (kt + 1 < nk) {
            stage_load(kt + 1, (kt + 1) & 1);
            asm volatile("cp.async.wait_group 1;\n");
        } else {
            asm volatile("cp.async.wait_group 0;\n");
        }
        __syncthreads();

        uint32_t stb = sb + st * STAGE_B;

        #pragma unroll
        for (int k32 = 0; k32 < 2; k32++) {
            uint32_t kb = k32 * 32 + akof;

            // phase 1: hh
            uint32_t ah[2][4], bh[4][2];
            #pragma unroll
            for (int mi = 0; mi < 2; mi++) {
                uint32_t ra = stb + (uint32_t)(wm * 32 + mi * 16 + arow) * ROWB + kb;
                LDSM4(ah[mi][0], ah[mi][1], ah[mi][2], ah[mi][3], ra + AHI_B);
            }
            #pragma unroll
            for (int nn = 0; nn < 2; nn++) {
                uint32_t rb = stb + (uint32_t)(wn * 32 + nn * 16 + arow) * ROWB + kb;
                uint32_t r0, r1, r2, r3;
                LDSM4(r0, r1, r2, r3, rb + BHI_B);
                bh[2*nn][0] = r0; bh[2*nn][1] = r2;
                bh[2*nn+1][0] = r1; bh[2*nn+1][1] = r3;
            }
            #pragma unroll
            for (int mi = 0; mi < 2; mi++)
                #pragma unroll
                for (int ni = 0; ni < 4; ni++)
                    MMA_S8(acc_h[mi][ni], ah[mi], bh[ni]);

            // phase 2: h * l'
            {
                uint32_t bl[4][2];
                #pragma unroll
                for (int nn = 0; nn < 2; nn++) {
                    uint32_t rb = stb + (uint32_t)(wn * 32 + nn * 16 + arow) * ROWB + kb;
                    uint32_t r0, r1, r2, r3;
                    LDSM4(r0, r1, r2, r3, rb + BLO_B);
                    bl[2*nn][0] = r0; bl[2*nn][1] = r2;
                    bl[2*nn+1][0] = r1; bl[2*nn+1][1] = r3;
                }
                #pragma unroll
                for (int mi = 0; mi < 2; mi++)
                    #pragma unroll
                    for (int ni = 0; ni < 4; ni++)
                        MMA_S8(acc_x[mi][ni], ah[mi], bl[ni]);
            }

            // phase 3: l * h'
            {
                uint32_t al[2][4];
                #pragma unroll
                for (int mi = 0; mi < 2; mi++) {
                    uint32_t ra = stb + (uint32_t)(wm * 32 + mi * 16 + arow) * ROWB + kb;
                    LDSM4(al[mi][0], al[mi][1], al[mi][2], al[mi][3], ra + ALO_B);
                }
                #pragma unroll
                for (int mi = 0; mi < 2; mi++)
                    #pragma unroll
                    for (int ni = 0; ni < 4; ni++)
                        MMA_S8(acc_x[mi][ni], al[mi], bh[ni]);
            }
        }
        __syncthreads();
    }

    // epilogue
    const float inv16129 = 1.0f / 16129.0f;
    const float inv254   = 1.0f / 254.0f;
    const float invSH    = 127.0f / S_H;
    #pragma unroll
    for (int mi = 0; mi < 2; mi++) {
        #pragma unroll
        for (int ni = 0; ni < 4; ni++) {
            int cn = nBase + wn * 32 + ni * 8 + 2 * tig;
            float f0 = Sw[cn]     * inv16129;
            float f1 = Sw[cn + 1] * inv16129;
            float b0 = bias[cn], b1 = bias[cn + 1];
            #pragma unroll
            for (int half = 0; half < 2; half++) {
                int rm = mBase + wm * 32 + mi * 16 + gid + half * 8;
                float sa = Sa ? Sa[rm] : saFixed;
                float v0 = sa * f0 * ((float)acc_h[mi][ni][half*2]   + (float)acc_x[mi][ni][half*2]   * inv254) + b0;
                float v1 = sa * f1 * ((float)acc_h[mi][ni][half*2+1] + (float)acc_x[mi][ni][half*2+1] * inv254) + b1;
                if (EPI == 0) {
                    if (cn < CDIM)     v0 *= 8.0f;
                    if (cn + 1 < CDIM) v1 *= 8.0f;
                    *(float2*)&C[(size_t)rm * N + cn] = make_float2(v0, v1);
                } else if (EPI == 1) {
                    if (rm < M) {
                        float2 r = *(const float2*)&R[(size_t)rm * N + cn];
                        *(float2*)&C[(size_t)rm * N + cn] = make_float2(v0 + r.x, v1 + r.y);
                    }
                } else {
                    v0 = 0.5f * v0 * (1.0f + erff(v0 * 0.70710678118654752f));
                    v1 = 0.5f * v1 * (1.0f + erff(v1 * 0.70710678118654752f));
                    int8_t h0,l0,h1,l1;
                    isplit(v0, invSH, h0, l0);
                    isplit(v1, invSH, h1, l1);
                    char2 hc; hc.x = h0; hc.y = h1;
                    char2 lc; lc.x = l0; lc.y = l1;
                    *(char2*)&Ch[(size_t)rm * N + cn] = hc;
                    *(char2*)&Cl[(size_t)rm * N + cn] = lc;
                }
            }
        }
    }
}

// ---------------------------------------------------------------------------
// Neighbor attention v2: 128 threads/block, 1 token. Warp covers 2 heads
// (16 lanes each); lane owns 4 channels via float4. which[] hoisted so all
// 16 gathers issue back-to-back. Output int8-split + per-row scale.
// ---------------------------------------------------------------------------
__global__ void attn_kernel(const float* __restrict__ qkv, const int* __restrict__ which,
                            const int* __restrict__ mask, int8_t* __restrict__ yh,
                            int8_t* __restrict__ yl, float* __restrict__ sa) {
    int t = blockIdx.x;
    int n = t / DEPTH, d = t % DEPTH;
    int wid  = threadIdx.x >> 5;       // 0..3
    int lane = threadIdx.x & 31;
    int hg   = lane >> 4;              // 0..1
    int h    = wid * 2 + hg;           // head 0..7
    int li   = lane & 15;              // 0..15, 4 channels each

    float4 q = ((const float4*)(qkv + (size_t)t * (3 * CDIM) + h * HD))[li];

    int nb[KNB];
    int mk[KNB];
    #pragma unroll
    for (int k = 0; k < KNB; k++) {
        nb[k] = which[n * KNB + k];
        mk[k] = mask[n * KNB + k];
    }

    float sc[KNB];
    float4 vv[KNB];
    #pragma unroll
    for (int k = 0; k < KNB; k++) {
        const float* base = qkv + (size_t)(nb[k] * DEPTH + d) * (3 * CDIM) + h * HD;
        float4 kv = ((const float4*)(base + CDIM))[li];
        vv[k]     = ((const float4*)(base + 2 * CDIM))[li];
        float dot = q.x * kv.x + q.y * kv.y + q.z * kv.z + q.w * kv.w;
        #pragma unroll
        for (int o = 8; o; o >>= 1) dot += __shfl_xor_sync(0xffffffffu, dot, o);
        sc[k] = (mk[k] > 0) ? dot : -1.0e9f;
    }

    float mx = sc[0];
    #pragma unroll
    for (int k = 1; k < KNB; k++) mx = fmaxf(mx, sc[k]);
    float wsum = 0.0f, w[KNB];
    #pragma unroll
    for (int k = 0; k < KNB; k++) { w[k] = __expf(sc[k] - mx); wsum += w[k]; }
    float inv = 1.0f / wsum;

    float4 acc = make_float4(0.0f, 0.0f, 0.0f, 0.0f);
    #pragma unroll
    for (int k = 0; k < KNB; k++) {
        acc.x += w[k] * vv[k].x;
        acc.y += w[k] * vv[k].y;
        acc.z += w[k] * vv[k].z;
        acc.w += w[k] * vv[k].w;
    }
    acc.x *= inv; acc.y *= inv; acc.z *= inv; acc.w *= inv;

    float m = fmaxf(fmaxf(fabsf(acc.x), fabsf(acc.y)),
                    fmaxf(fabsf(acc.z), fabsf(acc.w)));
    #pragma unroll
    for (int o = 8; o; o >>= 1) m = fmaxf(m, __shfl_xor_sync(0xffffffffu, m, o));
    __shared__ float am[8];
    if (li == 0) am[h] = m;
    __syncthreads();
    m = am[0];
    #pragma unroll
    for (int i = 1; i < 8; i++) m = fmaxf(m, am[i]);
    float s = fmaxf(m, 1e-20f), qinv = 127.0f / s;

    int8_t h0,l0,h1,l1,h2,l2,h3,l3;
    isplit(acc.x, qinv, h0, l0);
    isplit(acc.y, qinv, h1, l1);
    isplit(acc.z, qinv, h2, l2);
    isplit(acc.w, qinv, h3, l3);
    char4 hc; hc.x = h0; hc.y = h1; hc.z = h2; hc.w = h3;
    char4 lc; lc.x = l0; lc.y = l1; lc.z = l2; lc.w = l3;
    *(char4*)&yh[(size_t)t * CDIM + h * HD + 4 * li] = hc;
    *(char4*)&yl[(size_t)t * CDIM + h * HD + 4 * li] = lc;
    if (threadIdx.x == 0) sa[t] = s;
}

// ---------------------------------------------------------------------------
extern "C" void kernel_launch(void* const* d_in, const int* in_sizes, int n_in,
                              void* d_out, int out_size) {
    const float* x      = (const float*)d_in[0];
    const int*   which  = (const int*)  d_in[1];
    const int*   mask   = (const int*)  d_in[2];
    const float* ln1_w  = (const float*)d_in[3];
    const float* ln1_b  = (const float*)d_in[4];
    const float* qkv_w  = (const float*)d_in[5];
    const float* qkv_b  = (const float*)d_in[6];
    const float* proj_w = (const float*)d_in[7];
    const float* proj_b = (const float*)d_in[8];
    const float* ln2_w  = (const float*)d_in[9];
    const float* ln2_b  = (const float*)d_in[10];
    const float* fc1_w  = (const float*)d_in[11];
    const float* fc1_b  = (const float*)d_in[12];
    const float* fc2_w  = (const float*)d_in[13];
    const float* fc2_b  = (const float*)d_in[14];
    float* out = (float*)d_out;

    float *p_qkv, *p_x2, *p_sa1, *p_sa2;
    int8_t *p_xnh, *p_xnl, *p_yh, *p_yl, *p_hh, *p_hl;
    int8_t *p_wqh, *p_wql, *p_wph, *p_wpl, *p_w1h, *p_w1l, *p_w2h, *p_w2l;
    float *p_swq, *p_swp, *p_sw1, *p_sw2;
    cudaGetSymbolAddress((void**)&p_qkv, g_qkv);
    cudaGetSymbolAddress((void**)&p_x2,  g_x2);
    cudaGetSymbolAddress((void**)&p_sa1, g_sa1);
    cudaGetSymbolAddress((void**)&p_sa2, g_sa2);
    cudaGetSymbolAddress((void**)&p_xnh, g_xn_h);
    cudaGetSymbolAddress((void**)&p_xnl, g_xn_l);
    cudaGetSymbolAddress((void**)&p_yh,  g_y_h);
    cudaGetSymbolAddress((void**)&p_yl,  g_y_l);
    cudaGetSymbolAddress((void**)&p_hh,  g_h_h);
    cudaGetSymbolAddress((void**)&p_hl,  g_h_l);
    cudaGetSymbolAddress((void**)&p_wqh, g_wqkv_h);
    cudaGetSymbolAddress((void**)&p_wql, g_wqkv_l);
    cudaGetSymbolAddress((void**)&p_wph, g_wproj_h);
    cudaGetSymbolAddress((void**)&p_wpl, g_wproj_l);
    cudaGetSymbolAddress((void**)&p_w1h, g_wfc1_h);
    cudaGetSymbolAddress((void**)&p_w1l, g_wfc1_l);
    cudaGetSymbolAddress((void**)&p_w2h, g_wfc2_h);
    cudaGetSymbolAddress((void**)&p_w2l, g_wfc2_l);
    cudaGetSymbolAddress((void**)&p_swq, g_swqkv);
    cudaGetSymbolAddress((void**)&p_swp, g_swproj);
    cudaGetSymbolAddress((void**)&p_sw1, g_swfc1);
    cudaGetSymbolAddress((void**)&p_sw2, g_swfc2);

    cudaFuncSetAttribute(imma_gemm<0>, cudaFuncAttributeMaxDynamicSharedMemorySize, SMEM_BYTES);
    cudaFuncSetAttribute(imma_gemm<1>, cudaFuncAttributeMaxDynamicSharedMemorySize, SMEM_BYTES);
    cudaFuncSetAttribute(imma_gemm<2>, cudaFuncAttributeMaxDynamicSharedMemorySize, SMEM_BYTES);

    // weight quantization (per output row)
    wq_kernel<<<3*CDIM, 128>>>(qkv_w,  p_wqh, p_wql, p_swq, CDIM);
    wq_kernel<<<CDIM,   128>>>(proj_w, p_wph, p_wpl, p_swp, CDIM);
    wq_kernel<<<HIDD,   128>>>(fc1_w,  p_w1h, p_w1l, p_sw1, CDIM);
    wq_kernel<<<CDIM,   128>>>(fc2_w,  p_w2h, p_w2l, p_sw2, HIDD);

    // 1. LN1 -> int8 xn + sa1
    ln_kernel<<<MTOK, 128>>>(x, ln1_w, ln1_b, p_xnh, p_xnl, p_sa1);
    // 2. QKV GEMM (+ q scale) -> fp32 qkv   (N tiles of 64)
    imma_gemm<0><<<dim3(MT, 24), 256, SMEM_BYTES>>>(p_xnh, p_xnl, p_wqh, p_wql,
                                                    p_sa1, 0.0f, p_swq, qkv_b,
                                                    nullptr, p_qkv, nullptr, nullptr,
                                                    MTOK, 3 * CDIM, CDIM);
    // 3. attention -> int8 y + sa2
    attn_kernel<<<MTOK, 128>>>(p_qkv, which, mask, p_yh, p_yl, p_sa2);
    // 4. proj + residual(x) -> fp32 x2
    imma_gemm<1><<<dim3(MT, 8), 256, SMEM_BYTES>>>(p_yh, p_yl, p_wph, p_wpl,
                                                   p_sa2, 0.0f, p_swp, proj_b,
                                                   x, p_x2, nullptr, nullptr,
                                                   MTOK, CDIM, CDIM);
    // 5. LN2 -> int8 xn + sa1
    ln_kernel<<<MTOK, 128>>>(p_x2, ln2_w, ln2_b, p_xnh, p_xnl, p_sa1);
    // 6. fc1 + GELU -> int8 h (fixed scale S_H)
    imma_gemm<2><<<dim3(MT, 32), 256, SMEM_BYTES>>>(p_xnh, p_xnl, p_w1h, p_w1l,
                                                    p_sa1, 0.0f, p_sw1, fc1_b,
                                                    nullptr, nullptr, p_hh, p_hl,
                                                    MTOK, HIDD, CDIM);
    // 7. fc2 + residual(x2) -> out  (A scale fixed = S_H)
    imma_gemm<1><<<dim3(MT, 8), 256, SMEM_BYTES>>>(p_hh, p_hl, p_w2h, p_w2l,
                                                   nullptr, S_H, p_sw2, fc2_b,
                                                   p_x2, out, nullptr, nullptr,
                                                   MTOK, CDIM, HIDD);
    (void)in_sizes; (void)n_in; (void)out_size;
}